// round 13
// baseline (speedup 1.0000x reference)
#include <cuda_runtime.h>
#include <cstdint>
#include <cstddef>

#define NROWS   65536
#define NCLS    1000
#define DFEAT   256
#define MROWS   64
#define NCTA    (NROWS / MROWS)      /* 1024 */
#define KSTEPS  32
#define THREADS 256
#define MMA_U32 1024                 /* 2 wn x 8 li x 64 */
#define STG_U32 2048                 /* + DP section 128 dims x 8 */
#define BSLOTS  6
#define RAWSTR  36                   /* 144B row stride: 16B-aligned for int4 pack loads */
#define RAW_U32 (64 * RAWSTR)        /* 2304 */
#define ROWTSTR 12                   /* 48B: uint4-aligned, conflict-free */
#define ROWT_U32 (64 * ROWTSTR)      /* 768 per step */

/* smem offsets in u32 */
#define OFF_B    0
#define OFF_RAW  (BSLOTS * STG_U32)               /* 12288 */
#define OFF_FRAG (OFF_RAW + 4 * RAW_U32)          /* 21504 */
#define OFF_ROWT (OFF_FRAG + 4 * 512)             /* 23552 */
#define OFF_CSQ  (OFF_ROWT + 4 * ROWT_U32)        /* 26624 */
#define OFF_CNT  (OFF_CSQ + 512)                  /* 27136 */
#define OFF_RED  (OFF_CNT + 64)                   /* 27200 */
#define SMEM_U32 (OFF_RED + 8)                    /* 27208 -> 108832 B; x2 CTA = 217.7KB OK */

// ---------------- device scratch ----------------
__device__ __align__(16) uint32_t g_B[KSTEPS * STG_U32];  // 256 KB
__device__ float     g_csqf[1024];
__device__ __align__(8) uint32_t g_csqpk[512];
__device__ float     g_partial[NCTA];

// ---------------- ptx helpers ----------------
__device__ __forceinline__ uint32_t smem_u32(const void* p) {
    uint32_t a;
    asm("{ .reg .u64 t; cvta.to.shared.u64 t, %1; cvt.u32.u64 %0, t; }" : "=r"(a) : "l"(p));
    return a;
}
__device__ __forceinline__ void cp_async16(uint32_t dst, const void* src) {
    asm volatile("cp.async.cg.shared.global [%0], [%1], 16;" :: "r"(dst), "l"(src));
}
__device__ __forceinline__ void cp_async16z(uint32_t dst, const void* src, uint32_t nbytes) {
    asm volatile("cp.async.cg.shared.global [%0], [%1], 16, %2;"
                 :: "r"(dst), "l"(src), "r"(nbytes));
}
__device__ __forceinline__ void cp_commit()  { asm volatile("cp.async.commit_group;" ::: "memory"); }
__device__ __forceinline__ void cp_wait0()   { asm volatile("cp.async.wait_group 0;" ::: "memory"); }

__device__ __forceinline__ int dp4a(uint32_t a, uint32_t b, int c) {
    int r;
    asm("dp4a.s32.s32 %0, %1, %2, %3;" : "=r"(r) : "r"(a), "r"(b), "r"(c));
    return r;
}
__device__ __forceinline__ uint32_t pack01(int4 v) {
    uint32_t t0, t1, r;
    asm("prmt.b32 %0, %1, %2, 0x0040;" : "=r"(t0) : "r"((uint32_t)v.x), "r"((uint32_t)v.y));
    asm("prmt.b32 %0, %1, %2, 0x0040;" : "=r"(t1) : "r"((uint32_t)v.z), "r"((uint32_t)v.w));
    asm("prmt.b32 %0, %1, %2, 0x5410;" : "=r"(r)  : "r"(t0), "r"(t1));
    return r;
}
__device__ __forceinline__ void mma_s8(int* c, uint32_t a0, uint32_t a1, uint32_t a2, uint32_t a3,
                                       uint32_t b0, uint32_t b1) {
    asm volatile(
        "mma.sync.aligned.m16n8k32.row.col.s32.s8.s8.s32 "
        "{%0,%1,%2,%3}, {%4,%5,%6,%7}, {%8,%9}, {%0,%1,%2,%3};"
        : "+r"(c[0]), "+r"(c[1]), "+r"(c[2]), "+r"(c[3])
        : "r"(a0), "r"(a1), "r"(a2), "r"(a3), "r"(b0), "r"(b1));
}

// ================= prep kernels =================
__global__ void prep_csq(const float* __restrict__ cen) {
    int w = threadIdx.x >> 5, l = threadIdx.x & 31;
    int c = blockIdx.x * 8 + w;
    float s = 0.f;
    #pragma unroll
    for (int j = 0; j < 8; j++) { float v = cen[(size_t)c * DFEAT + l + j * 32]; s += v * v; }
    #pragma unroll
    for (int o = 16; o; o >>= 1) s += __shfl_xor_sync(0xffffffffu, s, o);
    if (l == 0) g_csqf[c] = s;
}

// B layout per step s (2048 u32):
//  MMA [0,1024): wn half 512: pairs p<4: q = wn*512 + p*128 + lane*4 + w4
//    w4: (li=2p,r0),(li=2p,r1),(li=2p+1,r0),(li=2p+1,r1); dim=(wn*8+li)*8+(lane>>2);
//    c0 = s*32+(lane&3)*4+r*16
//  DP [1024,2048): q2 = (dim-128)*8 + kw; c0 = s*32 + kw*4
__global__ void prep_b(const float* __restrict__ cen) {
    int e = blockIdx.x * 256 + threadIdx.x;      // 0..65535
    int s = e >> 11, q = e & 2047;
    int dim, c0;
    if (q < MMA_U32) {
        int wn = q >> 9, q2 = q & 511;
        int p = q2 >> 7, lane = (q2 >> 2) & 31, w4 = q2 & 3;
        int li = 2 * p + (w4 >> 1), r = w4 & 1;
        dim = (wn * 8 + li) * 8 + (lane >> 2);
        c0  = s * 32 + (lane & 3) * 4 + r * 16;
    } else {
        int q2 = q - MMA_U32;
        dim = 128 + (q2 >> 3);
        c0  = s * 32 + (q2 & 7) * 4;
    }
    uint32_t packed = 0;
    #pragma unroll
    for (int j = 0; j < 4; j++) {
        int c = c0 + j;
        int v = 0;
        if (c < NCLS) v = __float2int_rn(16.0f * cen[(size_t)c * DFEAT + dim]);
        packed |= (uint32_t)(v & 0xFF) << (8 * j);
    }
    g_B[e] = packed;

    if (blockIdx.x == 0) {
        int qq = threadIdx.x;
        uint32_t hi = 0, lo = 0;
        #pragma unroll
        for (int j = 0; j < 4; j++) {
            int c   = qq * 4 + j;
            int q16 = (c < NCLS) ? (int)rintf(64.0f * g_csqf[c]) : 0;
            int h   = q16 >> 8;
            int l8  = (q16 & 255) - 128;
            hi |= (uint32_t)(h  & 0xFF) << (8 * j);
            lo |= (uint32_t)(l8 & 0xFF) << (8 * j);
        }
        g_csqpk[qq * 2]     = hi;
        g_csqpk[qq * 2 + 1] = lo;
    }
}

__global__ void init_partials() {
    int i = blockIdx.x * 256 + threadIdx.x;
    if (i < NCTA) g_partial[i] = 0.f;
}

// ================= main kernel: 256 threads, 2 CTAs/SM, 1 barrier / 2 k-steps =============
__global__ void __launch_bounds__(THREADS, 2)
center_main(const int* __restrict__ gt, const float* __restrict__ feat) {
    extern __shared__ __align__(16) uint32_t sm[];
    int*   sCnt = (int*)(sm + OFF_CNT);
    float* sRed = (float*)(sm + OFF_RED);

    const int tid  = threadIdx.x, wid = tid >> 5, lane = tid & 31;
    const int wm   = wid & 3, wn = wid >> 2;
    const int gq   = lane >> 2, tig = lane & 3;
    const int rl   = wm * 16 + gq;
    const size_t rowbase = (size_t)blockIdx.x * MROWS;

    sm[OFF_CSQ + tid]       = g_csqpk[tid];
    sm[OFF_CSQ + 256 + tid] = g_csqpk[256 + tid];
    if (tid < 64) sCnt[tid] = 0;

    const uint32_t smb = smem_u32(sm);

    // pack-task constants
    const int fu  = tid * 2;
    const int pj  = fu & 3;
    const int plf = (fu >> 2) & 31;
    const int pwm = fu >> 7;
    const int prow = pwm * 16 + (plf >> 2);
    const int pkw  = (plf & 3) + (pj >> 1) * 4;

    // prologue: prefetch steps 0,1 (B + raw)
    #pragma unroll
    for (int e = 0; e < 2; e++) {
        #pragma unroll
        for (int j = 0; j < 2; j++) {
            int i4 = tid + j * 256;
            cp_async16(smb + (uint32_t)(OFF_B + e * STG_U32 + i4 * 4) * 4,
                       (const void*)(g_B + (size_t)e * STG_U32 + i4 * 4));
        }
        #pragma unroll
        for (int j = 0; j < 2; j++) {
            int c = tid + j * 256;
            int row = c >> 3, part = c & 7;
            int cb = e * 32 + part * 4;
            cp_async16z(smb + (uint32_t)(OFF_RAW + e * RAW_U32 + row * RAWSTR + part * 4) * 4,
                        (const void*)(gt + (rowbase + row) * NCLS + cb),
                        (cb + 4 <= NCLS) ? 16u : 0u);
        }
    }
    cp_commit();

    int acc[8][4];
    #pragma unroll
    for (int i = 0; i < 8; i++) { acc[i][0] = acc[i][1] = acc[i][2] = acc[i][3] = 0; }
    int pacc[32];
    #pragma unroll
    for (int j = 0; j < 32; j++) pacc[j] = 0;
    int cntA = 0, cntB = 0, accHi = 0, accLo = 0;

    for (int i = 0; i <= 16; i++) {
        cp_wait0();
        __syncthreads();

        // ---- pack steps 2i, 2i+1 into parity buffer i&1 ----
        if (i < 16) {
            #pragma unroll
            for (int e = 0; e < 2; e++) {
                int s = 2 * i + e;
                const uint32_t* rawp = sm + OFF_RAW + (s & 3) * RAW_U32;
                int4 v0 = *(const int4*)(rawp + prow * RAWSTR + pkw * 4);
                int4 v1 = *(const int4*)(rawp + (prow + 8) * RAWSTR + pkw * 4);
                uint32_t p0 = pack01(v0), p1 = pack01(v1);
                uint32_t* fb = sm + OFF_FRAG + ((i & 1) * 2 + e) * 512;
                *(uint2*)(fb + fu) = make_uint2(p0, p1);
                uint32_t* rt = sm + OFF_ROWT + ((i & 1) * 2 + e) * ROWT_U32;
                rt[prow * ROWTSTR + pkw]       = p0;
                rt[(prow + 8) * ROWTSTR + pkw] = p1;
            }
            // ---- prefetch steps 2i+2, 2i+3 ----
            if (i < 15) {
                #pragma unroll
                for (int e = 0; e < 2; e++) {
                    int fs = 2 * i + 2 + e;
                    int bs = fs % BSLOTS;
                    #pragma unroll
                    for (int j = 0; j < 2; j++) {
                        int i4 = tid + j * 256;
                        cp_async16(smb + (uint32_t)(OFF_B + bs * STG_U32 + i4 * 4) * 4,
                                   (const void*)(g_B + (size_t)fs * STG_U32 + i4 * 4));
                    }
                    int rs = fs & 3;
                    #pragma unroll
                    for (int j = 0; j < 2; j++) {
                        int c = tid + j * 256;
                        int row = c >> 3, part = c & 7;
                        int cb = fs * 32 + part * 4;
                        cp_async16z(smb + (uint32_t)(OFF_RAW + rs * RAW_U32 + row * RAWSTR + part * 4) * 4,
                                    (const void*)(gt + (rowbase + row) * NCLS + cb),
                                    (cb + 4 <= NCLS) ? 16u : 0u);
                    }
                }
            }
            cp_commit();
        }

        // ---- compute steps 2(i-1), 2(i-1)+1 from buffer (i-1)&1 ----
        if (i >= 1) {
            #pragma unroll
            for (int e = 0; e < 2; e++) {
                int s = 2 * (i - 1) + e;
                const int bs = s % BSLOTS;
                const uint32_t* fb = sm + OFF_FRAG + (((i - 1) & 1) * 2 + e) * 512;
                uint4 Af = *(const uint4*)(fb + (wm * 32 + lane) * 4);
                uint32_t A0 = Af.x, A1 = Af.y, A2 = Af.z, A3 = Af.w;

                // side term
                uint2 cqa = *(const uint2*)(sm + OFF_CSQ + (s * 8 + tig) * 2);
                uint2 cqb = *(const uint2*)(sm + OFF_CSQ + (s * 8 + tig + 4) * 2);
                cntA  = dp4a(A0, 0x01010101u, cntA);  cntA  = dp4a(A2, 0x01010101u, cntA);
                cntB  = dp4a(A1, 0x01010101u, cntB);  cntB  = dp4a(A3, 0x01010101u, cntB);
                accHi = dp4a(A0, cqa.x, accHi);       accHi = dp4a(A1, cqa.x, accHi);
                accHi = dp4a(A2, cqb.x, accHi);       accHi = dp4a(A3, cqb.x, accHi);
                accLo = dp4a(A0, cqa.y, accLo);       accLo = dp4a(A1, cqa.y, accLo);
                accLo = dp4a(A2, cqb.y, accLo);       accLo = dp4a(A3, cqb.y, accLo);

                // tensor path: 8 MMAs (4 paired uint4 loads)
                const uint32_t* bp = sm + OFF_B + bs * STG_U32 + wn * 512;
                #pragma unroll
                for (int p = 0; p < 4; p++) {
                    uint4 bb = *(const uint4*)(bp + p * 128 + lane * 4);
                    mma_s8(acc[2 * p],     A0, A1, A2, A3, bb.x, bb.y);
                    mma_s8(acc[2 * p + 1], A0, A1, A2, A3, bb.z, bb.w);
                }

                // dp4a path: rows (lane, lane+32), dims 128 + wid*16 .. +16
                {
                    const uint32_t* dpB = sm + OFF_B + bs * STG_U32 + MMA_U32 + wid * 128;
                    const uint32_t* rt  = sm + OFF_ROWT + (((i - 1) & 1) * 2 + e) * ROWT_U32;
                    const uint32_t* mr0 = rt + lane * ROWTSTR;
                    const uint32_t* mr1 = mr0 + 32 * ROWTSTR;
                    uint4 m0a = *(const uint4*)(mr0), m0b = *(const uint4*)(mr0 + 4);
                    uint4 m1a = *(const uint4*)(mr1), m1b = *(const uint4*)(mr1 + 4);
                    #pragma unroll
                    for (int d = 0; d < 16; d++) {
                        uint4 b0 = *(const uint4*)(dpB + d * 8);
                        uint4 b1 = *(const uint4*)(dpB + d * 8 + 4);
                        int a0 = pacc[d * 2], a1 = pacc[d * 2 + 1];
                        a0 = dp4a(m0a.x, b0.x, a0); a0 = dp4a(m0a.y, b0.y, a0);
                        a0 = dp4a(m0a.z, b0.z, a0); a0 = dp4a(m0a.w, b0.w, a0);
                        a0 = dp4a(m0b.x, b1.x, a0); a0 = dp4a(m0b.y, b1.y, a0);
                        a0 = dp4a(m0b.z, b1.z, a0); a0 = dp4a(m0b.w, b1.w, a0);
                        a1 = dp4a(m1a.x, b0.x, a1); a1 = dp4a(m1a.y, b0.y, a1);
                        a1 = dp4a(m1a.z, b0.z, a1); a1 = dp4a(m1a.w, b0.w, a1);
                        a1 = dp4a(m1b.x, b1.x, a1); a1 = dp4a(m1b.y, b1.y, a1);
                        a1 = dp4a(m1b.z, b1.z, a1); a1 = dp4a(m1b.w, b1.w, a1);
                        pacc[d * 2] = a0; pacc[d * 2 + 1] = a1;
                    }
                }
            }
        }
    }

    // ---- epilogue ----
    atomicAdd(&sCnt[rl],     cntA);
    atomicAdd(&sCnt[rl + 8], cntB);
    __syncthreads();

    // tensor side: rows rl, rl+8; dims wn*64 .. +64
    const float* f0 = feat + (rowbase + rl) * DFEAT + wn * 64 + tig * 2;
    const float* f1 = f0 + (size_t)8 * DFEAT;
    float cr = 0.f, s2a = 0.f, s2b = 0.f;
    #pragma unroll
    for (int li = 0; li < 8; li++) {
        float2 v0 = *(const float2*)(f0 + li * 8);
        float2 v1 = *(const float2*)(f1 + li * 8);
        cr  += v0.x * (float)acc[li][0] + v0.y * (float)acc[li][1]
             + v1.x * (float)acc[li][2] + v1.y * (float)acc[li][3];
        s2a += v0.x * v0.x + v0.y * v0.y;
        s2b += v1.x * v1.x + v1.y * v1.y;
    }
    int   c64i = accHi * 256 + accLo + 128 * (cntA + cntB);
    float thr = s2a * (0.5f * (float)sCnt[rl]) + s2b * (0.5f * (float)sCnt[rl + 8])
              + (float)c64i * (1.0f / 128.0f)
              - cr * 0.125f;

    // dp side: rows lane & lane+32; dims 128 + wid*16 .. +16
    #pragma unroll
    for (int h = 0; h < 2; h++) {
        int r = lane + h * 32;
        const float* fd = feat + (rowbase + r) * DFEAT + 128 + wid * 16;
        float crd = 0.f, s2d = 0.f;
        #pragma unroll
        for (int d = 0; d < 16; d++) {
            float v = fd[d];
            crd += v * (float)pacc[d * 2 + h];
            s2d += v * v;
        }
        thr += s2d * (0.5f * (float)sCnt[r]) - crd * 0.125f;
    }

    #pragma unroll
    for (int o = 16; o; o >>= 1) thr += __shfl_xor_sync(0xffffffffu, thr, o);
    if (lane == 0) sRed[wid] = thr;
    __syncthreads();
    if (tid == 0) {
        float v = 0.f;
        #pragma unroll
        for (int i = 0; i < 8; i++) v += sRed[i];
        g_partial[blockIdx.x] = v;
    }
}

__global__ void finalize_loss(float* __restrict__ out) {
    __shared__ float sr[8];
    int tid = threadIdx.x, wid = tid >> 5, lane = tid & 31;
    float v = 0.f;
    #pragma unroll
    for (int j = 0; j < 4; j++) v += g_partial[tid + j * 256];
    #pragma unroll
    for (int o = 16; o; o >>= 1) v += __shfl_xor_sync(0xffffffffu, v, o);
    if (lane == 0) sr[wid] = v;
    __syncthreads();
    if (wid == 0) {
        float t = (lane < 8) ? sr[lane] : 0.f;
        #pragma unroll
        for (int o = 4; o; o >>= 1) t += __shfl_xor_sync(0xffffffffu, t, o);
        if (lane == 0) out[0] = t * (1.0f / (float)NROWS);
    }
}

// ================= launch =================
extern "C" void kernel_launch(void* const* d_in, const int* in_sizes, int n_in,
                              void* d_out, int out_size) {
    const int*   gt   = (const int*)d_in[0];
    const float* feat = (const float*)d_in[1];
    const float* cen  = (const float*)d_in[2];
    float* out = (float*)d_out;

    cudaFuncSetAttribute(center_main, cudaFuncAttributeMaxDynamicSharedMemorySize,
                         SMEM_U32 * 4);

    prep_csq<<<125, 256>>>(cen);                           // 0
    prep_b<<<256, 256>>>(cen);                             // 1
    init_partials<<<4, 256>>>();                           // 2
    center_main<<<NCTA, THREADS, SMEM_U32 * 4>>>(gt, feat);// 3 — ncu capture slot
    finalize_loss<<<1, 256>>>(out);                        // 4
}

// round 15
// speedup vs baseline: 1.2115x; 1.2115x over previous
#include <cuda_runtime.h>
#include <cstdint>
#include <cstddef>

#define NROWS   65536
#define NCLS    1000
#define DFEAT   256
#define MROWS   32
#define NCTA    (NROWS / MROWS)      /* 2048 */
#define KSTEPS  32
#define THREADS 128
#define MMA_U32 1152                 /* 2 wn x (4 pairs x 128 + 64) */
#define STG_U32 2048                 /* + DP section 112 dims x 8 */
#define DPW     28                   /* dp dims per warp */

// ---------------- device scratch ----------------
__device__ __align__(16) uint32_t g_B[KSTEPS * STG_U32];  // 256 KB
__device__ float     g_csqf[1024];                        // zero-init pad
__device__ __align__(8) uint32_t g_csqpk[512];
__device__ float     g_partial[NCTA];

// ---------------- ptx helpers ----------------
__device__ __forceinline__ uint32_t smem_u32(const void* p) {
    uint32_t a;
    asm("{ .reg .u64 t; cvta.to.shared.u64 t, %1; cvt.u32.u64 %0, t; }" : "=r"(a) : "l"(p));
    return a;
}
__device__ __forceinline__ void cp_async16(uint32_t dst, const void* src) {
    asm volatile("cp.async.cg.shared.global [%0], [%1], 16;" :: "r"(dst), "l"(src));
}
__device__ __forceinline__ void cp_commit() { asm volatile("cp.async.commit_group;" ::: "memory"); }
__device__ __forceinline__ void cp_wait2()  { asm volatile("cp.async.wait_group 2;" ::: "memory"); }

__device__ __forceinline__ int dp4a(uint32_t a, uint32_t b, int c) {
    int r;
    asm("dp4a.s32.s32 %0, %1, %2, %3;" : "=r"(r) : "r"(a), "r"(b), "r"(c));
    return r;
}
__device__ __forceinline__ uint32_t pack01(int4 v) {
    uint32_t t0, t1, r;
    asm("prmt.b32 %0, %1, %2, 0x0040;" : "=r"(t0) : "r"((uint32_t)v.x), "r"((uint32_t)v.y));
    asm("prmt.b32 %0, %1, %2, 0x0040;" : "=r"(t1) : "r"((uint32_t)v.z), "r"((uint32_t)v.w));
    asm("prmt.b32 %0, %1, %2, 0x5410;" : "=r"(r)  : "r"(t0), "r"(t1));
    return r;
}
// 4 bits -> 4 mask bytes (bit j -> byte j = 0/1)
__device__ __forceinline__ uint32_t expand4(uint32_t n) {
    return (n * 0x00204081u) & 0x01010101u;
}
__device__ __forceinline__ void mma_s8(int* c, uint32_t a0, uint32_t a1, uint32_t a2, uint32_t a3,
                                       uint32_t b0, uint32_t b1) {
    asm volatile(
        "mma.sync.aligned.m16n8k32.row.col.s32.s8.s8.s32 "
        "{%0,%1,%2,%3}, {%4,%5,%6,%7}, {%8,%9}, {%0,%1,%2,%3};"
        : "+r"(c[0]), "+r"(c[1]), "+r"(c[2]), "+r"(c[3])
        : "r"(a0), "r"(a1), "r"(a2), "r"(a3), "r"(b0), "r"(b1));
}

// ================= prep kernels =================
__global__ void prep_csq(const float* __restrict__ cen) {
    int w = threadIdx.x >> 5, l = threadIdx.x & 31;
    int c = blockIdx.x * 8 + w;
    float s = 0.f;
    #pragma unroll
    for (int j = 0; j < 8; j++) { float v = cen[(size_t)c * DFEAT + l + j * 32]; s += v * v; }
    #pragma unroll
    for (int o = 16; o; o >>= 1) s += __shfl_xor_sync(0xffffffffu, s, o);
    if (l == 0) g_csqf[c] = s;
}

// B layout per step s (2048 u32):
//  MMA [0,1152): wn half 576: pairs p<4: q2<512: li=2p+(w4>>1), r=w4&1; single li=8 at +512.
//    dim=(wn*9+li)*8+(lane>>2); c0=s*32+(lane&3)*4+r*16
//  DP [1152,2048): q2=(dim-144)*8+kw; c0=s*32+kw*4
__global__ void prep_b(const float* __restrict__ cen) {
    int e = blockIdx.x * 256 + threadIdx.x;      // 0..65535
    int s = e >> 11, q = e & 2047;
    int dim, c0;
    if (q < MMA_U32) {
        int wn = q / 576, q2 = q - wn * 576;
        int li, lane, r;
        if (q2 < 512) {
            int p = q2 >> 7; lane = (q2 >> 2) & 31; int w4 = q2 & 3;
            li = 2 * p + (w4 >> 1); r = w4 & 1;
        } else {
            li = 8; lane = (q2 - 512) >> 1; r = q2 & 1;
        }
        dim = (wn * 9 + li) * 8 + (lane >> 2);
        c0  = s * 32 + (lane & 3) * 4 + r * 16;
    } else {
        int q2 = q - MMA_U32;
        dim = 144 + (q2 >> 3);
        c0  = s * 32 + (q2 & 7) * 4;
    }
    uint32_t packed = 0;
    #pragma unroll
    for (int j = 0; j < 4; j++) {
        int c = c0 + j;
        int v = 0;
        if (c < NCLS) v = __float2int_rn(16.0f * cen[(size_t)c * DFEAT + dim]);
        packed |= (uint32_t)(v & 0xFF) << (8 * j);
    }
    g_B[e] = packed;

    if (blockIdx.x == 0) {
        int qq = threadIdx.x;
        uint32_t hi = 0, lo = 0;
        #pragma unroll
        for (int j = 0; j < 4; j++) {
            int c   = qq * 4 + j;
            int q16 = (c < NCLS) ? (int)rintf(64.0f * g_csqf[c]) : 0;
            int h   = q16 >> 8;
            int l8  = (q16 & 255) - 128;
            hi |= (uint32_t)(h  & 0xFF) << (8 * j);
            lo |= (uint32_t)(l8 & 0xFF) << (8 * j);
        }
        g_csqpk[qq * 2]     = hi;
        g_csqpk[qq * 2 + 1] = lo;
    }
}

__global__ void init_partials() {
    int i = blockIdx.x * 256 + threadIdx.x;
    if (i < NCTA) g_partial[i] = 0.f;
}

// ================= main kernel: 128 threads, 4 CTAs/SM, bitmask masks =================
__global__ void __launch_bounds__(THREADS, 4)
center_main(const int* __restrict__ gt, const float* __restrict__ feat) {
    __shared__ __align__(16) uint32_t sB[4][STG_U32];     // 32 KB B ring
    __shared__ __align__(16) uint32_t sBits[KSTEPS * 32]; // [s][row] 4 KB
    __shared__ uint2 sCsq[256];
    __shared__ int   sCnt[32];
    __shared__ float sRed[4];

    const int tid  = threadIdx.x, wid = tid >> 5, lane = tid & 31;
    const int wm   = wid & 1, wn = wid >> 1;
    const int gq   = lane >> 2, tig = lane & 3;
    const int rl   = wm * 16 + gq;
    const size_t rowbase = (size_t)blockIdx.x * MROWS;

    sCsq[tid]       = *(const uint2*)&g_csqpk[tid * 2];
    sCsq[tid + 128] = *(const uint2*)&g_csqpk[(tid + 128) * 2];   // BUGFIX: upper half
    if (tid < 32) sCnt[tid] = 0;
    // zero bits tile (covers padded classes 1000..1023 tail)
    #pragma unroll
    for (int j = 0; j < 8; j++) sBits[tid + j * 128] = 0u;

    const uint32_t smb = smem_u32(&sB[0][0]);

    // B prefetch: stages 0..2 (512 int4 per stage / 128 threads = 4 each)
    #pragma unroll
    for (int s = 0; s < 3; s++) {
        #pragma unroll
        for (int j = 0; j < 4; j++)
            cp_async16(smb + (uint32_t)(s * STG_U32 + (j * 128 + tid) * 4) * 4,
                       (const void*)(g_B + (size_t)s * STG_U32 + (j * 128 + tid) * 4));
        cp_commit();
    }

    __syncthreads();   // zeros visible before byte writes

    // ---- prologue: gt (32 rows x 1000 int32) -> bit tile [s][row] ----
    {
        const int* gbase = gt + rowbase * NCLS;
        uint8_t* b8 = (uint8_t*)sBits;
        #pragma unroll 4
        for (int q = 0; q < 32; q++) {
            int idx2 = q * 128 + tid;           // int8-class-group index, 4000 total
            if (idx2 < 4000) {
                int row = idx2 / 125;
                int off = (idx2 - row * 125) * 8;  // class offset within row
                const int4* p4 = (const int4*)(gbase + (size_t)row * NCLS + off);
                int4 v0 = p4[0], v1 = p4[1];
                uint32_t n0 = (pack01(v0) * 0x01020408u) >> 24;  // bits for classes off..off+3
                uint32_t n1 = (pack01(v1) * 0x01020408u) >> 24;  // off+4..off+7
                int s = off >> 5, b = (off >> 3) & 3;
                b8[(s * 32 + row) * 4 + b] = (uint8_t)(n0 | (n1 << 4));
            }
        }
    }

    int acc[9][4];
    #pragma unroll
    for (int i = 0; i < 9; i++) { acc[i][0] = acc[i][1] = acc[i][2] = acc[i][3] = 0; }
    int pacc[DPW];
    #pragma unroll
    for (int j = 0; j < DPW; j++) pacc[j] = 0;
    int cntA = 0, cntB = 0, accHi = 0, accLo = 0;

    __syncthreads();   // bits tile complete

    for (int s = 0; s < KSTEPS; s++) {
        const int slot = s & 3;
        cp_wait2();
        __syncthreads();

        // masks for this step: own row word + frag rows via shfl
        uint32_t w  = sBits[s * 32 + lane];
        uint32_t w1 = __shfl_sync(0xffffffffu, w, rl);
        uint32_t w2 = __shfl_sync(0xffffffffu, w, rl + 8);
        uint32_t A0 = expand4((w1 >> (tig * 4)) & 0xFu);
        uint32_t A2 = expand4((w1 >> (16 + tig * 4)) & 0xFu);
        uint32_t A1 = expand4((w2 >> (tig * 4)) & 0xFu);
        uint32_t A3 = expand4((w2 >> (16 + tig * 4)) & 0xFu);

        // prefetch B stage s+3 (barrier above protects slot reuse)
        if (s + 3 < KSTEPS) {
            #pragma unroll
            for (int j = 0; j < 4; j++)
                cp_async16(smb + (uint32_t)(((s + 3) & 3) * STG_U32 + (j * 128 + tid) * 4) * 4,
                           (const void*)(g_B + (size_t)(s + 3) * STG_U32 + (j * 128 + tid) * 4));
        }
        cp_commit();

        // exact side term
        uint2 cqa = sCsq[s * 8 + tig];
        uint2 cqb = sCsq[s * 8 + tig + 4];
        cntA  = dp4a(A0, 0x01010101u, cntA);  cntA  = dp4a(A2, 0x01010101u, cntA);
        cntB  = dp4a(A1, 0x01010101u, cntB);  cntB  = dp4a(A3, 0x01010101u, cntB);
        accHi = dp4a(A0, cqa.x, accHi);       accHi = dp4a(A1, cqa.x, accHi);
        accHi = dp4a(A2, cqb.x, accHi);       accHi = dp4a(A3, cqb.x, accHi);
        accLo = dp4a(A0, cqa.y, accLo);       accLo = dp4a(A1, cqa.y, accLo);
        accLo = dp4a(A2, cqb.y, accLo);       accLo = dp4a(A3, cqb.y, accLo);

        // tensor path: 9 MMAs over dims wn*72 .. +72
        const uint32_t* bp = &sB[slot][wn * 576];
        #pragma unroll
        for (int p = 0; p < 4; p++) {
            uint4 bb = *(const uint4*)(bp + p * 128 + lane * 4);
            mma_s8(acc[2 * p],     A0, A1, A2, A3, bb.x, bb.y);
            mma_s8(acc[2 * p + 1], A0, A1, A2, A3, bb.z, bb.w);
        }
        {
            uint2 b8v = *(const uint2*)(bp + 512 + lane * 2);
            mma_s8(acc[8], A0, A1, A2, A3, b8v.x, b8v.y);
        }

        // dp4a path: row = lane, dims 144 + wid*28 .. +28
        {
            uint32_t mw[8];
            #pragma unroll
            for (int k = 0; k < 8; k++) mw[k] = expand4((w >> (4 * k)) & 0xFu);
            const uint32_t* dpB = &sB[slot][MMA_U32 + wid * (DPW * 8)];
            #pragma unroll
            for (int d = 0; d < DPW; d++) {
                uint4 b0 = *(const uint4*)(dpB + d * 8);
                uint4 b1 = *(const uint4*)(dpB + d * 8 + 4);
                int a = pacc[d];
                a = dp4a(mw[0], b0.x, a); a = dp4a(mw[1], b0.y, a);
                a = dp4a(mw[2], b0.z, a); a = dp4a(mw[3], b0.w, a);
                a = dp4a(mw[4], b1.x, a); a = dp4a(mw[5], b1.y, a);
                a = dp4a(mw[6], b1.z, a); a = dp4a(mw[7], b1.w, a);
                pacc[d] = a;
            }
        }
    }

    // ---- epilogue ----
    atomicAdd(&sCnt[rl],     cntA);
    atomicAdd(&sCnt[rl + 8], cntB);
    __syncthreads();

    // tensor side: rows rl, rl+8; dims wn*72 + li*8 + tig*2
    const float* f0 = feat + (rowbase + rl) * DFEAT + wn * 72 + tig * 2;
    const float* f1 = f0 + (size_t)8 * DFEAT;
    float cr = 0.f, s2a = 0.f, s2b = 0.f;
    #pragma unroll
    for (int li = 0; li < 9; li++) {
        float2 v0 = *(const float2*)(f0 + li * 8);
        float2 v1 = *(const float2*)(f1 + li * 8);
        cr  += v0.x * (float)acc[li][0] + v0.y * (float)acc[li][1]
             + v1.x * (float)acc[li][2] + v1.y * (float)acc[li][3];
        s2a += v0.x * v0.x + v0.y * v0.y;
        s2b += v1.x * v1.x + v1.y * v1.y;
    }
    int   c64i = accHi * 256 + accLo + 128 * (cntA + cntB);
    float thr = s2a * (0.5f * (float)sCnt[rl]) + s2b * (0.5f * (float)sCnt[rl + 8])
              + (float)c64i * (1.0f / 128.0f)
              - cr * 0.125f;

    // dp side: row = lane, dims 144 + wid*28 .. +28
    {
        const float* fd = feat + (rowbase + lane) * DFEAT + 144 + wid * DPW;
        float crd = 0.f, s2d = 0.f;
        #pragma unroll
        for (int j4 = 0; j4 < DPW / 4; j4++) {
            float4 v = *(const float4*)(fd + j4 * 4);
            crd += v.x * (float)pacc[j4 * 4 + 0] + v.y * (float)pacc[j4 * 4 + 1]
                 + v.z * (float)pacc[j4 * 4 + 2] + v.w * (float)pacc[j4 * 4 + 3];
            s2d += v.x * v.x + v.y * v.y + v.z * v.z + v.w * v.w;
        }
        thr += s2d * (0.5f * (float)sCnt[lane]) - crd * 0.125f;
    }

    #pragma unroll
    for (int o = 16; o; o >>= 1) thr += __shfl_xor_sync(0xffffffffu, thr, o);
    if (lane == 0) sRed[wid] = thr;
    __syncthreads();
    if (tid == 0)
        g_partial[blockIdx.x] = sRed[0] + sRed[1] + sRed[2] + sRed[3];
}

__global__ void finalize_loss(float* __restrict__ out) {
    __shared__ float sr[8];
    int tid = threadIdx.x, wid = tid >> 5, lane = tid & 31;
    float v = 0.f;
    #pragma unroll
    for (int j = 0; j < 8; j++) v += g_partial[tid + j * 256];
    #pragma unroll
    for (int o = 16; o; o >>= 1) v += __shfl_xor_sync(0xffffffffu, v, o);
    if (lane == 0) sr[wid] = v;
    __syncthreads();
    if (wid == 0) {
        float t = (lane < 8) ? sr[lane] : 0.f;
        #pragma unroll
        for (int o = 4; o; o >>= 1) t += __shfl_xor_sync(0xffffffffu, t, o);
        if (lane == 0) out[0] = t * (1.0f / (float)NROWS);
    }
}

// ================= launch =================
extern "C" void kernel_launch(void* const* d_in, const int* in_sizes, int n_in,
                              void* d_out, int out_size) {
    const int*   gt   = (const int*)d_in[0];
    const float* feat = (const float*)d_in[1];
    const float* cen  = (const float*)d_in[2];
    float* out = (float*)d_out;

    prep_csq<<<125, 256>>>(cen);              // 0
    prep_b<<<256, 256>>>(cen);                // 1
    init_partials<<<8, 256>>>();              // 2
    center_main<<<NCTA, THREADS>>>(gt, feat); // 3 — ncu capture slot
    finalize_loss<<<1, 256>>>(out);           // 4
}